// round 3
// baseline (speedup 1.0000x reference)
#include <cuda_runtime.h>
#include <cuda_bf16.h>

// Problem constants (fixed by the dataset):
//   acts: (B, T, U+1, V) fp32, labels: (B, U) int32, act_lens/label_lens: (B,) int32
#define BB  16
#define TT  200
#define UU  100
#define VV  256
#define UP1 101          // U + 1
#define NEG_INF (-1e30f)

// Scratch (no cudaMalloc allowed): log-probs of blank / emitted label per lattice node.
__device__ float g_blank[BB * TT * UP1];   // (B, T, U+1)
__device__ float g_emit [BB * TT * UU];    // (B, T, U)
__device__ float g_perb [BB];              // per-example nll / label_len

// ---------------------------------------------------------------------------
// Kernel 1: fused log-softmax gather. One warp per (b, t, u) node.
// Each lane loads 8 contiguous floats (2x float4) -> warp covers V=256.
// Writes blank_lp = acts[...,0] - logZ and emit_lp = acts[...,label[u]] - logZ.
// ---------------------------------------------------------------------------
__global__ __launch_bounds__(256) void rnnt_softmax_kernel(
    const float* __restrict__ acts,
    const int*   __restrict__ labels)
{
    const int P = BB * TT * UP1;
    int warp = blockIdx.x * (blockDim.x >> 5) + (threadIdx.x >> 5);
    if (warp >= P) return;
    int lane = threadIdx.x & 31;

    const float4* p = reinterpret_cast<const float4*>(acts) + (size_t)warp * (VV / 4);
    float4 a = p[lane];
    float4 b = p[lane + 32];

    float m = fmaxf(fmaxf(fmaxf(a.x, a.y), fmaxf(a.z, a.w)),
                    fmaxf(fmaxf(b.x, b.y), fmaxf(b.z, b.w)));
    #pragma unroll
    for (int o = 16; o; o >>= 1)
        m = fmaxf(m, __shfl_xor_sync(0xffffffffu, m, o));

    float s = __expf(a.x - m) + __expf(a.y - m) + __expf(a.z - m) + __expf(a.w - m)
            + __expf(b.x - m) + __expf(b.y - m) + __expf(b.z - m) + __expf(b.w - m);
    #pragma unroll
    for (int o = 16; o; o >>= 1)
        s += __shfl_xor_sync(0xffffffffu, s, o);

    if (lane == 0) {
        float logZ = m + __logf(s);
        int u  = warp % UP1;
        int bt = warp / UP1;               // b*T + t
        // lane 0's a.x is element 0 of this row: the blank logit.
        g_blank[warp] = a.x - logZ;
        if (u < UU) {
            int bidx = bt / TT;
            int lbl  = labels[bidx * UU + u];
            float lv = __ldg(acts + (size_t)warp * VV + lbl);  // L1-hot reload
            g_emit[bt * UU + u] = lv - logZ;
        }
    }
}

// ---------------------------------------------------------------------------
// Kernel 2: per-example forward DP, anti-diagonal wavefront in shared memory.
// alpha[t][u] = logaddexp(alpha[t-1][u] + blank[t-1][u],
//                         alpha[t][u-1] + emit[t][u-1])
// Both per-example tiles (blank: T*(U+1), emit: T*U) are staged into dynamic
// SMEM (160.8 KB) so the wavefront never touches global memory.
// ---------------------------------------------------------------------------
__global__ __launch_bounds__(128) void rnnt_dp_kernel(
    const int* __restrict__ act_lens,
    const int* __restrict__ label_lens)
{
    int b  = blockIdx.x;
    int Tl = act_lens[b];
    int Ul = label_lens[b];
    int tid = threadIdx.x;

    extern __shared__ float sm[];
    float* sb = sm;                 // TT * UP1 floats
    float* se = sm + TT * UP1;      // TT * UU  floats
    __shared__ float buf0[UP1 + 1];
    __shared__ float buf1[UP1 + 1];

    const float* gb = g_blank + b * TT * UP1;
    const float* ge = g_emit  + b * TT * UU;
    for (int i = tid; i < TT * UP1; i += blockDim.x) sb[i] = gb[i];
    for (int i = tid; i < TT * UU;  i += blockDim.x) se[i] = ge[i];

    if (tid <= UU) buf0[tid] = (tid == 0) ? 0.0f : NEG_INF;
    __syncthreads();

    float* pp = buf0;   // diagonal d-1, indexed by u  -> alpha(d-1-u, u)
    float* cc = buf1;

    int dmax = (Tl - 1) + Ul;
    for (int d = 1; d <= dmax; ++d) {
        int u = tid;
        if (u <= UU) {
            float val = NEG_INF;
            int t = d - u;
            if (u <= Ul && t >= 0 && t < Tl) {
                float fb = (t >= 1) ? pp[u]     + sb[(t - 1) * UP1 + u]   : NEG_INF;
                float fl = (u >= 1) ? pp[u - 1] + se[t * UU + (u - 1)]    : NEG_INF;
                float mx = fmaxf(fb, fl);
                float mn = fminf(fb, fl);
                val = mx + log1pf(__expf(mn - mx));
                if (t == Tl - 1 && u == Ul) {
                    float ll = val + sb[(Tl - 1) * UP1 + Ul];
                    g_perb[b] = -ll / (float)Ul;
                }
            }
            cc[u] = val;
        }
        __syncthreads();
        float* tmp = pp; pp = cc; cc = tmp;
    }
}

// ---------------------------------------------------------------------------
// Kernel 3: deterministic scalar reduction (mean over batch).
// ---------------------------------------------------------------------------
__global__ void rnnt_reduce_kernel(float* __restrict__ out)
{
    if (threadIdx.x == 0) {
        float s = 0.0f;
        #pragma unroll
        for (int i = 0; i < BB; ++i) s += g_perb[i];
        out[0] = s / (float)BB;
    }
}

extern "C" void kernel_launch(void* const* d_in, const int* in_sizes, int n_in,
                              void* d_out, int out_size)
{
    const float* acts       = (const float*)d_in[0];
    const int*   labels     = (const int*)  d_in[1];
    const int*   act_lens   = (const int*)  d_in[2];
    const int*   label_lens = (const int*)  d_in[3];
    float*       out        = (float*)d_out;

    const int P = BB * TT * UP1;            // warps needed
    const int warpsPerBlock = 8;            // 256 threads
    int blocks = (P + warpsPerBlock - 1) / warpsPerBlock;
    rnnt_softmax_kernel<<<blocks, 256>>>(acts, labels);

    size_t smem = (size_t)(TT * UP1 + TT * UU) * sizeof(float);  // 160,800 B
    cudaFuncSetAttribute(rnnt_dp_kernel,
                         cudaFuncAttributeMaxDynamicSharedMemorySize, (int)smem);
    rnnt_dp_kernel<<<BB, 128, smem>>>(act_lens, label_lens);

    rnnt_reduce_kernel<<<1, 32>>>(out);
}

// round 7
// speedup vs baseline: 1.0747x; 1.0747x over previous
#include <cuda_runtime.h>
#include <cuda_bf16.h>

// Problem constants (fixed by the dataset):
//   acts: (B, T, U+1, V) fp32, labels: (B, U) int32, act_lens/label_lens: (B,) int32
#define BB  16
#define TT  200
#define UU  100
#define VV  256
#define UP1 101          // U + 1
#define NEG_INF (-1e30f)

// Scratch (no cudaMalloc allowed).
__device__ float g_blank[BB * TT * UP1];   // (B, T, U+1)
__device__ float g_emit [BB * TT * UU];    // (B, T, U)
__device__ float g_perb [BB];              // per-example nll / label_len

// ---------------------------------------------------------------------------
// Kernel 1: fused log-softmax gather, one warp per (b, t, u) node.
// Skips nodes outside the live lattice region (t >= act_len or u > label_len):
// the DP never reads those, so we avoid ~43% of the DRAM traffic.
// ---------------------------------------------------------------------------
__global__ __launch_bounds__(256) void rnnt_softmax_kernel(
    const float* __restrict__ acts,
    const int*   __restrict__ labels,
    const int*   __restrict__ act_lens,
    const int*   __restrict__ label_lens)
{
    const int P = BB * TT * UP1;
    int warp = blockIdx.x * (blockDim.x >> 5) + (threadIdx.x >> 5);
    if (warp >= P) return;
    int lane = threadIdx.x & 31;

    int u    = warp % UP1;
    int bt   = warp / UP1;       // b*T + t
    int t    = bt % TT;
    int bidx = bt / TT;

    // Live-region skip (lengths are tiny, L2/L1-hot broadcast loads).
    if (t >= __ldg(act_lens + bidx) || u > __ldg(label_lens + bidx)) return;

    const float4* p = reinterpret_cast<const float4*>(acts) + (size_t)warp * (VV / 4);
    float4 a = p[lane];
    float4 b = p[lane + 32];

    float m = fmaxf(fmaxf(fmaxf(a.x, a.y), fmaxf(a.z, a.w)),
                    fmaxf(fmaxf(b.x, b.y), fmaxf(b.z, b.w)));
    #pragma unroll
    for (int o = 16; o; o >>= 1)
        m = fmaxf(m, __shfl_xor_sync(0xffffffffu, m, o));

    float s = __expf(a.x - m) + __expf(a.y - m) + __expf(a.z - m) + __expf(a.w - m)
            + __expf(b.x - m) + __expf(b.y - m) + __expf(b.z - m) + __expf(b.w - m);
    #pragma unroll
    for (int o = 16; o; o >>= 1)
        s += __shfl_xor_sync(0xffffffffu, s, o);

    if (lane == 0) {
        float logZ = m + __logf(s);
        // lane 0's a.x is element 0 of this row: the blank logit.
        g_blank[warp] = a.x - logZ;
        if (u < UU) {
            int lbl  = labels[bidx * UU + u];
            float lv = __ldg(acts + (size_t)warp * VV + lbl);  // L1-hot reload
            g_emit[bt * UU + u] = lv - logZ;
        }
    }
}

// ---------------------------------------------------------------------------
// Kernel 2: per-example forward DP, anti-diagonal wavefront held entirely in
// registers of ONE warp. Lane l owns u in {l, l+32, l+64, l+96}. The u-1
// dependency across the diagonal is a shfl_up (+ lane-31 broadcast at the
// 32-boundary). No __syncthreads in the loop, no smem alpha buffers.
// blank/emit tiles (t < Tl rows only) are staged into smem once (each element
// is consumed exactly once).
// ---------------------------------------------------------------------------
__global__ __launch_bounds__(128) void rnnt_dp_kernel(
    const int* __restrict__ act_lens,
    const int* __restrict__ label_lens)
{
    int b   = blockIdx.x;
    int Tl  = act_lens[b];
    int Ul  = label_lens[b];
    int tid = threadIdx.x;

    extern __shared__ float sm[];
    float* sb = sm;                 // TT * UP1 floats
    float* se = sm + TT * UP1;      // TT * UU  floats

    const float* gb = g_blank + b * TT * UP1;
    const float* ge = g_emit  + b * TT * UU;
    for (int i = tid; i < Tl * UP1; i += 128) sb[i] = gb[i];
    for (int i = tid; i < Tl * UU;  i += 128) se[i] = ge[i];
    __syncthreads();
    if (tid >= 32) return;

    const unsigned F = 0xffffffffu;
    int l = tid;

    // alpha on previous diagonal for u = l + 32k (diag 0: only (t=0,u=0)=0).
    float pp0 = (l == 0) ? 0.0f : NEG_INF;
    float pp1 = NEG_INF, pp2 = NEG_INF, pp3 = NEG_INF;

    int dmax = (Tl - 1) + Ul;
    for (int d = 1; d <= dmax; ++d) {
        // Left-neighbor (u-1) values from the previous diagonal.
        float s0 = __shfl_up_sync(F, pp0, 1);
        float s1 = __shfl_up_sync(F, pp1, 1);
        float s2 = __shfl_up_sync(F, pp2, 1);
        float s3 = __shfl_up_sync(F, pp3, 1);
        float w1 = __shfl_sync(F, pp0, 31);
        float w2 = __shfl_sync(F, pp1, 31);
        float w3 = __shfl_sync(F, pp2, 31);
        if (l == 0) { s0 = NEG_INF; s1 = w1; s2 = w2; s3 = w3; }

        float np0 = NEG_INF, np1 = NEG_INF, np2 = NEG_INF, np3 = NEG_INF;

        #pragma unroll
        for (int k = 0; k < 4; ++k) {
            int u = l + 32 * k;
            int t = d - u;
            float pk = (k == 0) ? pp0 : (k == 1) ? pp1 : (k == 2) ? pp2 : pp3;
            float sk = (k == 0) ? s0  : (k == 1) ? s1  : (k == 2) ? s2  : s3;
            if (u <= Ul && t >= 0 && t < Tl) {
                float fb = (t >= 1) ? pk + sb[(t - 1) * UP1 + u] : NEG_INF;
                float fl = (u >= 1) ? sk + se[t * UU + (u - 1)]  : NEG_INF;
                float mx = fmaxf(fb, fl);
                float mn = fminf(fb, fl);
                float nv = mx + __logf(1.0f + __expf(mn - mx));
                if (t == Tl - 1 && u == Ul)
                    g_perb[b] = -(nv + sb[(Tl - 1) * UP1 + Ul]) / (float)Ul;
                if      (k == 0) np0 = nv;
                else if (k == 1) np1 = nv;
                else if (k == 2) np2 = nv;
                else             np3 = nv;
            }
        }
        pp0 = np0; pp1 = np1; pp2 = np2; pp3 = np3;
    }
}

// ---------------------------------------------------------------------------
// Kernel 3: deterministic scalar reduction (mean over batch).
// ---------------------------------------------------------------------------
__global__ void rnnt_reduce_kernel(float* __restrict__ out)
{
    if (threadIdx.x == 0) {
        float s = 0.0f;
        #pragma unroll
        for (int i = 0; i < BB; ++i) s += g_perb[i];
        out[0] = s / (float)BB;
    }
}

extern "C" void kernel_launch(void* const* d_in, const int* in_sizes, int n_in,
                              void* d_out, int out_size)
{
    const float* acts       = (const float*)d_in[0];
    const int*   labels     = (const int*)  d_in[1];
    const int*   act_lens   = (const int*)  d_in[2];
    const int*   label_lens = (const int*)  d_in[3];
    float*       out        = (float*)d_out;

    const int P = BB * TT * UP1;            // one warp per lattice node
    const int warpsPerBlock = 8;            // 256 threads
    int blocks = (P + warpsPerBlock - 1) / warpsPerBlock;
    rnnt_softmax_kernel<<<blocks, 256>>>(acts, labels, act_lens, label_lens);

    size_t smem = (size_t)(TT * UP1 + TT * UU) * sizeof(float);  // 160,800 B
    cudaFuncSetAttribute(rnnt_dp_kernel,
                         cudaFuncAttributeMaxDynamicSharedMemorySize, (int)smem);
    rnnt_dp_kernel<<<BB, 128, smem>>>(act_lens, label_lens);

    rnnt_reduce_kernel<<<1, 32>>>(out);
}

// round 8
// speedup vs baseline: 1.4934x; 1.3897x over previous
#include <cuda_runtime.h>
#include <cuda_bf16.h>

// Problem constants (fixed by the dataset):
//   acts: (B, T, U+1, V) fp32, labels: (B, U) int32, act_lens/label_lens: (B,) int32
#define BB  16
#define TT  200
#define UU  100
#define VV  256
#define UP1 101          // U + 1
#define NEG_INF (-1e30f)

// Scratch (no cudaMalloc allowed).
__device__ float    g_blank[BB * TT * UP1];   // (B, T, U+1)
__device__ float    g_emit [BB * TT * UU];    // (B, T, U)
__device__ float    g_perb [BB];              // per-example nll / label_len
__device__ unsigned g_done = 0;               // block-completion counter

// ---------------------------------------------------------------------------
// Kernel 1: fused log-softmax gather, TWO (b,t,u) nodes per warp (MLP=4).
// Skips nodes outside the live lattice region (t >= act_len or u > label_len).
// ---------------------------------------------------------------------------
__global__ __launch_bounds__(256) void rnnt_softmax_kernel(
    const float* __restrict__ acts,
    const int*   __restrict__ labels,
    const int*   __restrict__ act_lens,
    const int*   __restrict__ label_lens)
{
    const int P = BB * TT * UP1;                       // 323200 (even)
    int w    = blockIdx.x * 8 + (threadIdx.x >> 5);    // warp id
    int lane = threadIdx.x & 31;
    int n0   = w * 2;
    if (n0 >= P) return;
    int n1 = n0 + 1;

    // Decode both nodes.
    int u0 = n0 % UP1, bt0 = n0 / UP1, t0 = bt0 % TT, b0i = bt0 / TT;
    int u1 = n1 % UP1, bt1 = n1 / UP1, t1 = bt1 % TT, b1i = bt1 / TT;

    bool L0 = (t0 < __ldg(act_lens + b0i)) && (u0 <= __ldg(label_lens + b0i));
    bool L1 = (t1 < __ldg(act_lens + b1i)) && (u1 <= __ldg(label_lens + b1i));
    if (!L0 && !L1) return;

    const float4* p0 = reinterpret_cast<const float4*>(acts) + (size_t)n0 * (VV / 4);
    const float4* p1 = p0 + (VV / 4);

    float4 a0 = {0,0,0,0}, c0 = {0,0,0,0}, a1 = {0,0,0,0}, c1 = {0,0,0,0};
    if (L0) { a0 = p0[lane]; c0 = p0[lane + 32]; }
    if (L1) { a1 = p1[lane]; c1 = p1[lane + 32]; }

    float m0 = fmaxf(fmaxf(fmaxf(a0.x, a0.y), fmaxf(a0.z, a0.w)),
                     fmaxf(fmaxf(c0.x, c0.y), fmaxf(c0.z, c0.w)));
    float m1 = fmaxf(fmaxf(fmaxf(a1.x, a1.y), fmaxf(a1.z, a1.w)),
                     fmaxf(fmaxf(c1.x, c1.y), fmaxf(c1.z, c1.w)));
    #pragma unroll
    for (int o = 16; o; o >>= 1) {
        m0 = fmaxf(m0, __shfl_xor_sync(0xffffffffu, m0, o));
        m1 = fmaxf(m1, __shfl_xor_sync(0xffffffffu, m1, o));
    }

    float s0 = __expf(a0.x - m0) + __expf(a0.y - m0) + __expf(a0.z - m0) + __expf(a0.w - m0)
             + __expf(c0.x - m0) + __expf(c0.y - m0) + __expf(c0.z - m0) + __expf(c0.w - m0);
    float s1 = __expf(a1.x - m1) + __expf(a1.y - m1) + __expf(a1.z - m1) + __expf(a1.w - m1)
             + __expf(c1.x - m1) + __expf(c1.y - m1) + __expf(c1.z - m1) + __expf(c1.w - m1);
    #pragma unroll
    for (int o = 16; o; o >>= 1) {
        s0 += __shfl_xor_sync(0xffffffffu, s0, o);
        s1 += __shfl_xor_sync(0xffffffffu, s1, o);
    }

    if (lane == 0) {
        if (L0) {
            float logZ = m0 + __logf(s0);
            g_blank[n0] = a0.x - logZ;                 // a0.x on lane0 = blank logit
            if (u0 < UU) {
                int lbl  = labels[b0i * UU + u0];
                float lv = __ldg(acts + (size_t)n0 * VV + lbl);
                g_emit[bt0 * UU + u0] = lv - logZ;
            }
        }
        if (L1) {
            float logZ = m1 + __logf(s1);
            g_blank[n1] = a1.x - logZ;
            if (u1 < UU) {
                int lbl  = labels[b1i * UU + u1];
                float lv = __ldg(acts + (size_t)n1 * VV + lbl);
                g_emit[bt1 * UU + u1] = lv - logZ;
            }
        }
    }
}

// ---------------------------------------------------------------------------
// Kernel 2: per-example forward DP, anti-diagonal wavefront in one warp's
// registers. BRANCH-FREE inner loop: addresses are clamped into bounds and
// values masked with selects; the terminal-cell extraction happens AFTER the
// loop via shfl, so the loop body compiles to pure predicated arithmetic.
// Final mean-reduction is fused via a completion counter (no 3rd kernel).
// ---------------------------------------------------------------------------
__global__ __launch_bounds__(128) void rnnt_dp_kernel(
    const int* __restrict__ act_lens,
    const int* __restrict__ label_lens,
    float*     __restrict__ out)
{
    int b   = blockIdx.x;
    int Tl  = act_lens[b];
    int Ul  = label_lens[b];
    int tid = threadIdx.x;

    extern __shared__ float sm[];
    float* sb = sm;                 // TT * UP1 floats
    float* se = sm + TT * UP1;      // TT * UU  floats

    // float4 staging (both per-b slabs are 16B-aligned: 160800 and 80000 bytes).
    {
        const float4* gb4 = reinterpret_cast<const float4*>(g_blank + (size_t)b * TT * UP1);
        const float4* ge4 = reinterpret_cast<const float4*>(g_emit  + (size_t)b * TT * UU);
        float4* sb4 = reinterpret_cast<float4*>(sb);
        float4* se4 = reinterpret_cast<float4*>(se);
        int nb4 = (Tl * UP1 + 3) >> 2;   // <= 10050
        int ne4 = (Tl * UU  + 3) >> 2;   // <= 5000
        for (int i = tid; i < nb4; i += 128) sb4[i] = gb4[i];
        for (int i = tid; i < ne4; i += 128) se4[i] = ge4[i];
    }
    __syncthreads();
    if (tid >= 32) return;

    const unsigned F = 0xffffffffu;
    int l = tid;

    // alpha on previous diagonal for u = l + 32k (diag 0: only (0,0)=0).
    float pp0 = (l == 0) ? 0.0f : NEG_INF;
    float pp1 = NEG_INF, pp2 = NEG_INF, pp3 = NEG_INF;

    int dmax = (Tl - 1) + Ul;
    for (int d = 1; d <= dmax; ++d) {
        // u-1 neighbors from the previous diagonal (lane-carry at 32-boundary).
        float s0 = __shfl_up_sync(F, pp0, 1);
        float s1 = __shfl_up_sync(F, pp1, 1);
        float s2 = __shfl_up_sync(F, pp2, 1);
        float s3 = __shfl_up_sync(F, pp3, 1);
        float w1 = __shfl_sync(F, pp0, 31);
        float w2 = __shfl_sync(F, pp1, 31);
        float w3 = __shfl_sync(F, pp2, 31);
        s0 = (l == 0) ? NEG_INF : s0;
        s1 = (l == 0) ? w1 : s1;
        s2 = (l == 0) ? w2 : s2;
        s3 = (l == 0) ? w3 : s3;

        float np[4];
        float pk[4] = {pp0, pp1, pp2, pp3};
        float sk[4] = {s0, s1, s2, s3};

        #pragma unroll
        for (int k = 0; k < 4; ++k) {
            int u = l + 32 * k;
            int t = d - u;
            bool vu = (u <= Ul) && (t >= 0) && (t < Tl);
            bool vb = vu && (t >= 1);
            bool vl = vu && (u >= 1);
            // Clamped, always-in-bounds addresses; values masked below.
            int tb = min(max(t - 1, 0), TT - 1);
            int te = min(max(t,     0), TT - 1);
            int uc = min(u, UU);
            int ue = min(max(u - 1, 0), UU - 1);
            float bv = sb[tb * UP1 + uc];
            float ev = se[te * UU  + ue];
            float fb = vb ? pk[k] + bv : NEG_INF;
            float fl = vl ? sk[k] + ev : NEG_INF;
            float mx = fmaxf(fb, fl);
            float mn = fminf(fb, fl);
            float nv = mx + __logf(1.0f + __expf(mn - mx));
            np[k] = vu ? nv : NEG_INF;
        }
        pp0 = np[0]; pp1 = np[1]; pp2 = np[2]; pp3 = np[3];
    }

    // Terminal cell (t=Tl-1, u=Ul) sits in lane (Ul&31), register (Ul>>5).
    int lf = Ul & 31, kf = Ul >> 5;
    float v0 = __shfl_sync(F, pp0, lf);
    float v1 = __shfl_sync(F, pp1, lf);
    float v2 = __shfl_sync(F, pp2, lf);
    float v3 = __shfl_sync(F, pp3, lf);
    float v  = (kf == 0) ? v0 : (kf == 1) ? v1 : (kf == 2) ? v2 : v3;

    if (l == 0) {
        g_perb[b] = -(v + sb[(Tl - 1) * UP1 + Ul]) / (float)Ul;
        __threadfence();
        unsigned done = atomicAdd(&g_done, 1u);
        if (done == BB - 1) {                 // last example: fold the mean
            __threadfence();
            float s = 0.0f;
            #pragma unroll
            for (int i = 0; i < BB; ++i) s += __ldcg(&g_perb[i]);
            out[0] = s / (float)BB;
            g_done = 0;                       // reset for next graph replay
        }
    }
}

extern "C" void kernel_launch(void* const* d_in, const int* in_sizes, int n_in,
                              void* d_out, int out_size)
{
    const float* acts       = (const float*)d_in[0];
    const int*   labels     = (const int*)  d_in[1];
    const int*   act_lens   = (const int*)  d_in[2];
    const int*   label_lens = (const int*)  d_in[3];
    float*       out        = (float*)d_out;

    const int P     = BB * TT * UP1;          // lattice nodes
    const int pairs = P / 2;                  // two nodes per warp
    int blocks = (pairs + 7) / 8;             // 8 warps per 256-thread block
    rnnt_softmax_kernel<<<blocks, 256>>>(acts, labels, act_lens, label_lens);

    size_t smem = (size_t)(TT * UP1 + TT * UU) * sizeof(float);  // 160,800 B
    cudaFuncSetAttribute(rnnt_dp_kernel,
                         cudaFuncAttributeMaxDynamicSharedMemorySize, (int)smem);
    rnnt_dp_kernel<<<BB, 128, smem>>>(act_lens, label_lens, out);
}

// round 9
// speedup vs baseline: 1.8536x; 1.2412x over previous
#include <cuda_runtime.h>
#include <cuda_bf16.h>

// Problem constants (fixed by the dataset):
//   acts: (B, T, U+1, V) fp32, labels: (B, U) int32, act_lens/label_lens: (B,) int32
#define BB  16
#define TT  200
#define UU  100
#define VV  256
#define UP1 101          // U + 1
#define NEG_INF (-1e30f)

// Scratch (no cudaMalloc allowed).
__device__ float    g_blank[BB * TT * UP1];   // (B, T, U+1)
__device__ float    g_emit [BB * TT * UU];    // (B, T, U)
__device__ float    g_perb [BB];              // per-example nll / label_len
__device__ unsigned g_done = 0;               // block-completion counter

// ---------------------------------------------------------------------------
// Kernel 1: fused log-softmax gather, TWO (b,t,u) nodes per warp (MLP=4).
// Skips nodes outside the live lattice region (t >= act_len or u > label_len).
// ---------------------------------------------------------------------------
__global__ __launch_bounds__(256) void rnnt_softmax_kernel(
    const float* __restrict__ acts,
    const int*   __restrict__ labels,
    const int*   __restrict__ act_lens,
    const int*   __restrict__ label_lens)
{
    const int P = BB * TT * UP1;                       // 323200 (even)
    int w    = blockIdx.x * 8 + (threadIdx.x >> 5);    // warp id
    int lane = threadIdx.x & 31;
    int n0   = w * 2;
    if (n0 >= P) return;
    int n1 = n0 + 1;

    int u0 = n0 % UP1, bt0 = n0 / UP1, t0 = bt0 % TT, b0i = bt0 / TT;
    int u1 = n1 % UP1, bt1 = n1 / UP1, t1 = bt1 % TT, b1i = bt1 / TT;

    bool L0 = (t0 < __ldg(act_lens + b0i)) && (u0 <= __ldg(label_lens + b0i));
    bool L1 = (t1 < __ldg(act_lens + b1i)) && (u1 <= __ldg(label_lens + b1i));
    if (!L0 && !L1) return;

    const float4* p0 = reinterpret_cast<const float4*>(acts) + (size_t)n0 * (VV / 4);
    const float4* p1 = p0 + (VV / 4);

    float4 a0 = {0,0,0,0}, c0 = {0,0,0,0}, a1 = {0,0,0,0}, c1 = {0,0,0,0};
    if (L0) { a0 = p0[lane]; c0 = p0[lane + 32]; }
    if (L1) { a1 = p1[lane]; c1 = p1[lane + 32]; }

    float m0 = fmaxf(fmaxf(fmaxf(a0.x, a0.y), fmaxf(a0.z, a0.w)),
                     fmaxf(fmaxf(c0.x, c0.y), fmaxf(c0.z, c0.w)));
    float m1 = fmaxf(fmaxf(fmaxf(a1.x, a1.y), fmaxf(a1.z, a1.w)),
                     fmaxf(fmaxf(c1.x, c1.y), fmaxf(c1.z, c1.w)));
    #pragma unroll
    for (int o = 16; o; o >>= 1) {
        m0 = fmaxf(m0, __shfl_xor_sync(0xffffffffu, m0, o));
        m1 = fmaxf(m1, __shfl_xor_sync(0xffffffffu, m1, o));
    }

    float s0 = __expf(a0.x - m0) + __expf(a0.y - m0) + __expf(a0.z - m0) + __expf(a0.w - m0)
             + __expf(c0.x - m0) + __expf(c0.y - m0) + __expf(c0.z - m0) + __expf(c0.w - m0);
    float s1 = __expf(a1.x - m1) + __expf(a1.y - m1) + __expf(a1.z - m1) + __expf(a1.w - m1)
             + __expf(c1.x - m1) + __expf(c1.y - m1) + __expf(c1.z - m1) + __expf(c1.w - m1);
    #pragma unroll
    for (int o = 16; o; o >>= 1) {
        s0 += __shfl_xor_sync(0xffffffffu, s0, o);
        s1 += __shfl_xor_sync(0xffffffffu, s1, o);
    }

    if (lane == 0) {
        if (L0) {
            float logZ = m0 + __logf(s0);
            g_blank[n0] = a0.x - logZ;                 // a0.x on lane0 = blank logit
            if (u0 < UU) {
                int lbl  = labels[b0i * UU + u0];
                float lv = __ldg(acts + (size_t)n0 * VV + lbl);
                g_emit[bt0 * UU + u0] = lv - logZ;
            }
        }
        if (L1) {
            float logZ = m1 + __logf(s1);
            g_blank[n1] = a1.x - logZ;
            if (u1 < UU) {
                int lbl  = labels[b1i * UU + u1];
                float lv = __ldg(acts + (size_t)n1 * VV + lbl);
                g_emit[bt1 * UU + u1] = lv - logZ;
            }
        }
    }
}

// ---------------------------------------------------------------------------
// Kernel 2: per-example forward DP, anti-diagonal wavefront spread over FOUR
// warps (u = 32*warp + lane, one cell per lane). Per diagonal each warp issues
// only 2 MUFU ops (on its own SMSP), one shfl_up for the in-warp u-1 neighbor,
// and exchanges its lane-31 alpha with the next warp through a double-buffered
// smem slot guarded by a single __syncthreads. Branch-free body.
// Final mean-reduction fused via completion counter.
// ---------------------------------------------------------------------------
__global__ __launch_bounds__(128) void rnnt_dp_kernel(
    const int* __restrict__ act_lens,
    const int* __restrict__ label_lens,
    float*     __restrict__ out)
{
    int b   = blockIdx.x;
    int Tl  = act_lens[b];
    int Ul  = label_lens[b];
    int tid = threadIdx.x;
    int w   = tid >> 5;
    int l   = tid & 31;

    extern __shared__ float sm[];
    float* sb = sm;                 // TT * UP1 floats
    float* se = sm + TT * UP1;      // TT * UU  floats
    __shared__ float bd[2][4];      // per-warp lane-31 alpha, double-buffered

    // float4 staging of the live rows (slabs are 16B-aligned per example).
    {
        const float4* gb4 = reinterpret_cast<const float4*>(g_blank + (size_t)b * TT * UP1);
        const float4* ge4 = reinterpret_cast<const float4*>(g_emit  + (size_t)b * TT * UU);
        float4* sb4 = reinterpret_cast<float4*>(sb);
        float4* se4 = reinterpret_cast<float4*>(se);
        int nb4 = (Tl * UP1 + 3) >> 2;
        int ne4 = (Tl * UU  + 3) >> 2;
        for (int i = tid; i < nb4; i += 128) sb4[i] = gb4[i];
        for (int i = tid; i < ne4; i += 128) se4[i] = ge4[i];
    }
    if (tid < 8) bd[tid >> 2][tid & 3] = NEG_INF;
    __syncthreads();

    const unsigned F = 0xffffffffu;
    int u = w * 32 + l;                       // fixed u per lane (0..127)

    // Pre-clamped column indices (u never changes).
    int uc = min(u, UU);                      // for sb column
    int ue = min(max(u - 1, 0), UU - 1);      // for se column

    // alpha on previous diagonal at this u (diag 0: only (0,0)=0).
    float pp = (u == 0) ? 0.0f : NEG_INF;

    int dmax = (Tl - 1) + Ul;
    for (int d = 1; d <= dmax; ++d) {
        // u-1 neighbor from previous diagonal.
        float lf = __shfl_up_sync(F, pp, 1);
        float cross = (w > 0) ? bd[(d - 1) & 1][w - 1] : NEG_INF;
        lf = (l == 0) ? cross : lf;

        int t = d - u;
        bool vu = (u <= Ul) & (t >= 0) & (t < Tl);
        bool vb = vu & (t >= 1);
        bool vl = vu & (u >= 1);

        int tb = min(max(t - 1, 0), TT - 1);
        int te = min(max(t,     0), TT - 1);
        float bvv = sb[tb * UP1 + uc];
        float evv = se[te * UU  + ue];

        float fb = vb ? pp + bvv : NEG_INF;
        float fl = vl ? lf + evv : NEG_INF;
        float mx = fmaxf(fb, fl);
        float mn = fminf(fb, fl);
        float nv = mx + __logf(1.0f + __expf(mn - mx));
        pp = vu ? nv : NEG_INF;

        if (l == 31) bd[d & 1][w] = pp;
        __syncthreads();
    }

    // Terminal cell: lane with u == Ul holds alpha(Tl-1, Ul) after last diag.
    if (u == Ul) {
        g_perb[b] = -(pp + sb[(Tl - 1) * UP1 + Ul]) / (float)Ul;
        __threadfence();
        unsigned done = atomicAdd(&g_done, 1u);
        if (done == BB - 1) {                 // last example: fold the mean
            __threadfence();
            float s = 0.0f;
            #pragma unroll
            for (int i = 0; i < BB; ++i) s += __ldcg(&g_perb[i]);
            out[0] = s / (float)BB;
            g_done = 0;                       // reset for next graph replay
        }
    }
}

extern "C" void kernel_launch(void* const* d_in, const int* in_sizes, int n_in,
                              void* d_out, int out_size)
{
    const float* acts       = (const float*)d_in[0];
    const int*   labels     = (const int*)  d_in[1];
    const int*   act_lens   = (const int*)  d_in[2];
    const int*   label_lens = (const int*)  d_in[3];
    float*       out        = (float*)d_out;

    const int P     = BB * TT * UP1;          // lattice nodes
    const int pairs = P / 2;                  // two nodes per warp
    int blocks = (pairs + 7) / 8;             // 8 warps per 256-thread block
    rnnt_softmax_kernel<<<blocks, 256>>>(acts, labels, act_lens, label_lens);

    size_t smem = (size_t)(TT * UP1 + TT * UU) * sizeof(float);  // 160,800 B
    cudaFuncSetAttribute(rnnt_dp_kernel,
                         cudaFuncAttributeMaxDynamicSharedMemorySize, (int)smem);
    rnnt_dp_kernel<<<BB, 128, smem>>>(act_lens, label_lens, out);
}